// round 14
// baseline (speedup 1.0000x reference)
#include <cuda_runtime.h>

// Problem constants (fixed by the reference)
#define NN  50000
#define EE  800000
#define FIN 256
#define HH  128
#define CC  40
#define LPA_ITERS 10
#define NB  ((NN + 255) / 256)   // 196 scan blocks

// ---------------------------------------------------------------------------
// Device scratch (no allocations allowed)
// ---------------------------------------------------------------------------
__device__ __align__(128) float g_h1[(size_t)NN * HH];    // (features@W1)*ns
__device__ __align__(128) float g_agg1[(size_t)NN * HH];  // aggregated L1 (*nd fused)
__device__ __align__(128) float g_h2[(size_t)NN * CC];    // (x1@W2)*ns
__device__ __align__(128) float g_z[2][(size_t)NN * CC];  // LPA ping-pong
__device__ __align__(128) float g_ns[NN];
__device__ __align__(128) float g_nd[NN];

__device__ int g_deg_d[NN], g_deg_s[NN];
__device__ int g_off_d[NN + 1], g_off_s[NN + 1];
__device__ int g_cur_d[NN], g_cur_s[NN];
__device__ int g_csr_src[EE];                 // by-dst: src list
__device__ int g_csr_dst[EE];                 // by-src: dst list
__device__ int g_bsum_d[256], g_bsum_s[256];

// ---------------------------------------------------------------------------
// Init: zero degree/cursor ints; seed BOTH z buffers:
//   masked rows  = labels (never overwritten later -> read-side select vanishes)
//   unmasked     = 0
// ---------------------------------------------------------------------------
__global__ void k_init(const int* __restrict__ mask, const float* __restrict__ labels) {
    int i = blockIdx.x * blockDim.x + threadIdx.x;
    if (i < NN) { g_deg_d[i] = 0; g_deg_s[i] = 0; g_cur_d[i] = 0; g_cur_s[i] = 0; }
    if (i < NN * CC) {
        int r = i / CC;
        float v = (__ldg(mask + r) != 0) ? labels[i] : 0.0f;
        g_z[0][i] = v;
        g_z[1][i] = v;
    }
}

__global__ void k_hist(const int* __restrict__ src, const int* __restrict__ dst) {
    int e = blockIdx.x * blockDim.x + threadIdx.x;
    if (e >= EE) return;
    atomicAdd(&g_deg_s[src[e]], 1);
    atomicAdd(&g_deg_d[dst[e]], 1);
}

__global__ void k_norm() {
    int i = blockIdx.x * blockDim.x + threadIdx.x;
    if (i >= NN) return;
    g_ns[i] = rsqrtf((float)max(g_deg_s[i], 1));
    g_nd[i] = rsqrtf((float)max(g_deg_d[i], 1));
}

// ---------------------------------------------------------------------------
// 3-kernel exclusive scan (n <= 256*256)
// ---------------------------------------------------------------------------
__global__ void k_scan1(const int* __restrict__ deg, int* __restrict__ bsum, int n) {
    __shared__ int s[256];
    int t = threadIdx.x, i = blockIdx.x * 256 + t;
    s[t] = (i < n) ? deg[i] : 0;
    __syncthreads();
    for (int o = 128; o > 0; o >>= 1) {
        if (t < o) s[t] += s[t + o];
        __syncthreads();
    }
    if (t == 0) bsum[blockIdx.x] = s[0];
}

__global__ void k_scan2(int* __restrict__ bsum, int nb) {
    __shared__ int s[256];
    int t = threadIdx.x;
    s[t] = (t < nb) ? bsum[t] : 0;
    __syncthreads();
    for (int o = 1; o < 256; o <<= 1) {
        int v = (t >= o) ? s[t - o] : 0;
        __syncthreads();
        s[t] += v;
        __syncthreads();
    }
    if (t < nb) bsum[t] = (t == 0) ? 0 : s[t - 1];
}

__global__ void k_scan3(const int* __restrict__ deg, const int* __restrict__ boff,
                        int* __restrict__ off, int n) {
    __shared__ int s[256];
    int t = threadIdx.x, i = blockIdx.x * 256 + t;
    int v = (i < n) ? deg[i] : 0;
    s[t] = v;
    __syncthreads();
    for (int o = 1; o < 256; o <<= 1) {
        int u = (t >= o) ? s[t - o] : 0;
        __syncthreads();
        s[t] += u;
        __syncthreads();
    }
    if (i < n) off[i] = boff[blockIdx.x] + s[t] - v;
    if (i == n - 1) off[n] = boff[blockIdx.x] + s[t];
}

__global__ void k_fill(const int* __restrict__ src, const int* __restrict__ dst) {
    int e = blockIdx.x * blockDim.x + threadIdx.x;
    if (e >= EE) return;
    int s = src[e], d = dst[e];
    int pd = g_off_d[d] + atomicAdd(&g_cur_d[d], 1);
    g_csr_src[pd] = s;
    int ps = g_off_s[s] + atomicAdd(&g_cur_s[s], 1);
    g_csr_dst[ps] = d;
}

// ---------------------------------------------------------------------------
// GEMM1: g_h1 = (features[NN,FIN] @ W1[FIN,HH]) * ns[row]
// 128x128x16 tiles, 256 threads, 8x8 microtile: 64 FFMA per 4 LDS.128 per k.
// ---------------------------------------------------------------------------
__global__ void __launch_bounds__(256, 2)
k_gemm1(const float* __restrict__ A, const float* __restrict__ B) {
    __shared__ __align__(16) float As[16][132];  // [k][row]
    __shared__ __align__(16) float Bs[16][128];  // [k][col]

    const int tid = threadIdx.x;
    const int bm0 = blockIdx.x * 128;
    const int tx = tid & 15, ty = tid >> 4;

    float acc[8][8] = {};

    for (int k0 = 0; k0 < FIN; k0 += 16) {
        // Stage A: 128 rows x 16 k = 512 float4; 2 per thread
#pragma unroll
        for (int u = 0; u < 2; u++) {
            int l = tid * 2 + u;
            int row = l >> 2, kq = l & 3;
            int gr = bm0 + row;
            float4 av = (gr < NN)
                ? *(const float4*)(A + (size_t)gr * FIN + k0 + kq * 4)
                : make_float4(0.f, 0.f, 0.f, 0.f);
            As[kq * 4 + 0][row] = av.x;
            As[kq * 4 + 1][row] = av.y;
            As[kq * 4 + 2][row] = av.z;
            As[kq * 4 + 3][row] = av.w;
        }
        // Stage B: 16 k x 128 cols = 512 float4; 2 per thread
#pragma unroll
        for (int u = 0; u < 2; u++) {
            int l = tid * 2 + u;
            int kk = l >> 5, cq = l & 31;
            *(float4*)&Bs[kk][cq * 4] =
                *(const float4*)(B + (size_t)(k0 + kk) * HH + cq * 4);
        }
        __syncthreads();

#pragma unroll
        for (int k = 0; k < 16; k++) {
            float4 a0 = *(const float4*)&As[k][ty * 8];
            float4 a1 = *(const float4*)&As[k][ty * 8 + 4];
            float4 b0 = *(const float4*)&Bs[k][tx * 8];
            float4 b1 = *(const float4*)&Bs[k][tx * 8 + 4];
            float ar[8] = {a0.x, a0.y, a0.z, a0.w, a1.x, a1.y, a1.z, a1.w};
            float br[8] = {b0.x, b0.y, b0.z, b0.w, b1.x, b1.y, b1.z, b1.w};
#pragma unroll
            for (int i = 0; i < 8; i++)
#pragma unroll
                for (int j = 0; j < 8; j++)
                    acc[i][j] += ar[i] * br[j];
        }
        __syncthreads();
    }

#pragma unroll
    for (int i = 0; i < 8; i++) {
        int r = bm0 + ty * 8 + i;
        if (r < NN) {
            float ns = g_ns[r];
            float4 o0 = make_float4(acc[i][0] * ns, acc[i][1] * ns,
                                    acc[i][2] * ns, acc[i][3] * ns);
            float4 o1 = make_float4(acc[i][4] * ns, acc[i][5] * ns,
                                    acc[i][6] * ns, acc[i][7] * ns);
            *(float4*)(g_h1 + (size_t)r * HH + tx * 8) = o0;
            *(float4*)(g_h1 + (size_t)r * HH + tx * 8 + 4) = o1;
        }
    }
}

// ---------------------------------------------------------------------------
// Aggregate L1 (by-dst CSR): agg1[n] = (sum h1[s]) * nd[n]
// Warp per node, 32 lanes x float4 = full 128-wide row per neighbor.
// ---------------------------------------------------------------------------
__global__ void k_agg1() {
    int w = (blockIdx.x * blockDim.x + threadIdx.x) >> 5;
    if (w >= NN) return;
    int lane = threadIdx.x & 31;
    int beg = g_off_d[w], end = g_off_d[w + 1];

    float4 acc = make_float4(0.f, 0.f, 0.f, 0.f);
    for (int base = beg; base < end; base += 32) {
        int idx = (base + lane < end) ? g_csr_src[base + lane] : 0;
        int m = min(32, end - base);
        for (int j = 0; j < m; j++) {
            int s = __shfl_sync(0xffffffffu, idx, j);
            float4 v = *(const float4*)(g_h1 + (size_t)s * HH + lane * 4);
            acc.x += v.x; acc.y += v.y; acc.z += v.z; acc.w += v.w;
        }
    }
    float nd = g_nd[w];
    acc.x *= nd; acc.y *= nd; acc.z *= nd; acc.w *= nd;
    *(float4*)(g_agg1 + (size_t)w * HH + lane * 4) = acc;
}

// ---------------------------------------------------------------------------
// GEMM2 fused: g_h2 = (relu(agg1 + b1) @ W2[HH,CC]) * ns
// 32 rows/block, 320 threads: thread = (row, 4-col group), float4 W reads.
// ---------------------------------------------------------------------------
__global__ void k_gemm2(const float* __restrict__ W2, const float* __restrict__ b1) {
    __shared__ __align__(16) float sW[HH * CC];   // 20 KB
    __shared__ __align__(16) float sX[32][HH];    // 16 KB

    const int tid = threadIdx.x;  // 320
    for (int i = tid; i < (HH * CC) / 4; i += 320)
        ((float4*)sW)[i] = ((const float4*)W2)[i];

    const int row0 = blockIdx.x * 32;
    for (int i = tid; i < 32 * HH / 4; i += 320) {
        int r = i >> 5, cq = i & 31;
        int gr = row0 + r;
        float4 v = make_float4(0.f, 0.f, 0.f, 0.f);
        if (gr < NN) {
            v = *(const float4*)(g_agg1 + (size_t)gr * HH + cq * 4);
            float4 bb = *(const float4*)(b1 + cq * 4);
            v.x = fmaxf(v.x + bb.x, 0.f);
            v.y = fmaxf(v.y + bb.y, 0.f);
            v.z = fmaxf(v.z + bb.z, 0.f);
            v.w = fmaxf(v.w + bb.w, 0.f);
        }
        *(float4*)&sX[r][cq * 4] = v;
    }
    __syncthreads();

    const int cj4 = tid % 10, ri = tid / 10;  // ri 0..31
    float4 acc = make_float4(0.f, 0.f, 0.f, 0.f);
#pragma unroll 8
    for (int k = 0; k < HH; k++) {
        float x = sX[ri][k];
        float4 wv = *(const float4*)&sW[k * CC + cj4 * 4];
        acc.x += x * wv.x; acc.y += x * wv.y;
        acc.z += x * wv.z; acc.w += x * wv.w;
    }
    int gr = row0 + ri;
    if (gr < NN) {
        float ns = g_ns[gr];
        acc.x *= ns; acc.y *= ns; acc.z *= ns; acc.w *= ns;
        *(float4*)(g_h2 + (size_t)gr * CC + cj4 * 4) = acc;
    }
}

// ---------------------------------------------------------------------------
// Aggregate L2 + epilogue: out_x[n] = (sum h2[s]) * nd[n] + b2
// Warp per node, 3 neighbors/step: lane = jsub*10 + c, float4 per lane.
// ---------------------------------------------------------------------------
__global__ void k_agg2(float* __restrict__ out, const float* __restrict__ b2) {
    int w = (blockIdx.x * blockDim.x + threadIdx.x) >> 5;
    if (w >= NN) return;
    int lane = threadIdx.x & 31;
    int jsub = lane / 10;              // 0..2 active, 3 = idle lanes 30,31
    int c = lane - jsub * 10;
    int beg = g_off_d[w], end = g_off_d[w + 1];

    float4 acc = make_float4(0.f, 0.f, 0.f, 0.f);
    for (int base = beg; base < end; base += 32) {
        int m = min(32, end - base);
        int idx = (base + lane < end) ? g_csr_src[base + lane] : 0;
        for (int t = 0; t * 3 < m; t++) {
            int j = t * 3 + jsub;
            int s = __shfl_sync(0xffffffffu, idx, j & 31);
            if (jsub < 3 && j < m) {
                float4 v = *(const float4*)(g_h2 + (size_t)s * CC + c * 4);
                acc.x += v.x; acc.y += v.y; acc.z += v.z; acc.w += v.w;
            }
        }
    }
    float4 s1, s2;
    s1.x = __shfl_down_sync(0xffffffffu, acc.x, 10);
    s1.y = __shfl_down_sync(0xffffffffu, acc.y, 10);
    s1.z = __shfl_down_sync(0xffffffffu, acc.z, 10);
    s1.w = __shfl_down_sync(0xffffffffu, acc.w, 10);
    s2.x = __shfl_down_sync(0xffffffffu, acc.x, 20);
    s2.y = __shfl_down_sync(0xffffffffu, acc.y, 20);
    s2.z = __shfl_down_sync(0xffffffffu, acc.z, 20);
    s2.w = __shfl_down_sync(0xffffffffu, acc.w, 20);
    if (lane < 10) {
        float nd = g_nd[w];
        float4 bb = *(const float4*)(b2 + lane * 4);
        float4 o;
        o.x = (acc.x + s1.x + s2.x) * nd + bb.x;
        o.y = (acc.y + s1.y + s2.y) * nd + bb.y;
        o.z = (acc.z + s1.z + s2.z) * nd + bb.z;
        o.w = (acc.w + s1.w + s2.w) * nd + bb.w;
        *(float4*)(out + (size_t)w * CC + lane * 4) = o;
    }
}

// ---------------------------------------------------------------------------
// LPA iteration (by-src CSR), unmasked sources only, plain zin reads
// (masked rows of z hold labels). 3 neighbors/step layout as in k_agg2.
// ---------------------------------------------------------------------------
__global__ void k_lpa(const int* __restrict__ mask, const float* __restrict__ zin,
                      float* __restrict__ zout) {
    int w = (blockIdx.x * blockDim.x + threadIdx.x) >> 5;
    if (w >= NN) return;
    if (__ldg(mask + w) != 0) return;   // masked rows never consumed
    int lane = threadIdx.x & 31;
    int jsub = lane / 10;
    int c = lane - jsub * 10;
    int beg = g_off_s[w], end = g_off_s[w + 1];

    float4 acc = make_float4(0.f, 0.f, 0.f, 0.f);
    for (int base = beg; base < end; base += 32) {
        int m = min(32, end - base);
        int idx = (base + lane < end) ? g_csr_dst[base + lane] : 0;
        for (int t = 0; t * 3 < m; t++) {
            int j = t * 3 + jsub;
            int d = __shfl_sync(0xffffffffu, idx, j & 31);
            if (jsub < 3 && j < m) {
                float4 v = *(const float4*)(zin + (size_t)d * CC + c * 4);
                acc.x += v.x; acc.y += v.y; acc.z += v.z; acc.w += v.w;
            }
        }
    }
    float4 s1, s2;
    s1.x = __shfl_down_sync(0xffffffffu, acc.x, 10);
    s1.y = __shfl_down_sync(0xffffffffu, acc.y, 10);
    s1.z = __shfl_down_sync(0xffffffffu, acc.z, 10);
    s1.w = __shfl_down_sync(0xffffffffu, acc.w, 10);
    s2.x = __shfl_down_sync(0xffffffffu, acc.x, 20);
    s2.y = __shfl_down_sync(0xffffffffu, acc.y, 20);
    s2.z = __shfl_down_sync(0xffffffffu, acc.z, 20);
    s2.w = __shfl_down_sync(0xffffffffu, acc.w, 20);
    if (lane < 10) {
        float4 o;
        o.x = acc.x + s1.x + s2.x;
        o.y = acc.y + s1.y + s2.y;
        o.z = acc.z + s1.z + s2.z;
        o.w = acc.w + s1.w + s2.w;
        *(float4*)(zout + (size_t)w * CC + lane * 4) = o;
    }
}

// Fill masked output rows with labels (unmasked written by final k_lpa)
__global__ void k_epi_mask(float* __restrict__ out, const float* __restrict__ labels,
                           const int* __restrict__ mask) {
    int i = blockIdx.x * blockDim.x + threadIdx.x;
    if (i >= NN * CC) return;
    int r = i / CC;
    if (__ldg(mask + r) != 0) out[NN * CC + i] = labels[i];
}

// ---------------------------------------------------------------------------
// Launch
// ---------------------------------------------------------------------------
extern "C" void kernel_launch(void* const* d_in, const int* in_sizes, int n_in,
                              void* d_out, int out_size) {
    const float* feat   = (const float*)d_in[0];
    const float* labels = (const float*)d_in[1];
    const int*   mask   = (const int*)d_in[2];
    const int*   src    = (const int*)d_in[3];
    const int*   dst    = (const int*)d_in[4];
    const float* W1     = (const float*)d_in[5];
    const float* b1     = (const float*)d_in[6];
    const float* W2     = (const float*)d_in[7];
    const float* b2     = (const float*)d_in[8];
    float*       out    = (float*)d_out;

    const int T = 256;
    auto blks = [](long long n, int t) { return (int)((n + t - 1) / t); };

    void *p_deg_d, *p_deg_s, *p_off_d, *p_off_s, *p_bs_d, *p_bs_s, *p_z;
    cudaGetSymbolAddress(&p_deg_d, g_deg_d);
    cudaGetSymbolAddress(&p_deg_s, g_deg_s);
    cudaGetSymbolAddress(&p_off_d, g_off_d);
    cudaGetSymbolAddress(&p_off_s, g_off_s);
    cudaGetSymbolAddress(&p_bs_d, g_bsum_d);
    cudaGetSymbolAddress(&p_bs_s, g_bsum_s);
    cudaGetSymbolAddress(&p_z, g_z);
    float* z0 = (float*)p_z;
    float* z1 = z0 + (size_t)NN * CC;

    // 1-3: init + degrees + norms
    k_init<<<blks((long long)NN * CC, T), T>>>(mask, labels);
    k_hist<<<blks(EE, T), T>>>(src, dst);
    k_norm<<<blks(NN, T), T>>>();

    // 4: GEMM1 (positioned here so ncu's capture window hits it)
    k_gemm1<<<blks(NN, 128), 256>>>(feat, W1);

    // CSR build
    k_scan1<<<NB, 256>>>((const int*)p_deg_d, (int*)p_bs_d, NN);
    k_scan2<<<1, 256>>>((int*)p_bs_d, NB);
    k_scan3<<<NB, 256>>>((const int*)p_deg_d, (const int*)p_bs_d, (int*)p_off_d, NN);
    k_scan1<<<NB, 256>>>((const int*)p_deg_s, (int*)p_bs_s, NN);
    k_scan2<<<1, 256>>>((int*)p_bs_s, NB);
    k_scan3<<<NB, 256>>>((const int*)p_deg_s, (const int*)p_bs_s, (int*)p_off_s, NN);
    k_fill<<<blks(EE, T), T>>>(src, dst);

    // GCN
    k_agg1<<<blks((long long)NN * 32, T), T>>>();
    k_gemm2<<<blks(NN, 32), 320>>>(W2, b1);
    k_agg2<<<blks((long long)NN * 32, T), T>>>(out, b2);

    // LPA: ping-pong, final iteration writes straight into out
    for (int it = 0; it < LPA_ITERS; it++) {
        float* zin  = (it & 1) ? z1 : z0;
        float* zout = (it == LPA_ITERS - 1) ? (out + (size_t)NN * CC)
                                            : ((it & 1) ? z0 : z1);
        k_lpa<<<blks((long long)NN * 32, T), T>>>(mask, zin, zout);
    }
    k_epi_mask<<<blks((long long)NN * CC, T), T>>>(out, labels, mask);
}

// round 15
// speedup vs baseline: 1.0248x; 1.0248x over previous
#include <cuda_runtime.h>

// Problem constants (fixed by the reference)
#define NN  50000
#define EE  800000
#define FIN 256
#define HH  128
#define CC  40
#define LPA_ITERS 10
#define NB  ((NN + 255) / 256)   // 196 scan blocks

// ---------------------------------------------------------------------------
// Device scratch (no allocations allowed)
// ---------------------------------------------------------------------------
__device__ __align__(128) float g_h1[(size_t)NN * HH];    // (features@W1)*ns
__device__ __align__(128) float g_agg1[(size_t)NN * HH];  // aggregated L1 (*nd fused)
__device__ __align__(128) float g_h2[(size_t)NN * CC];    // (x1@W2)*ns
__device__ __align__(128) float g_z[2][(size_t)NN * CC];  // LPA ping-pong
__device__ __align__(128) float g_ns[NN];
__device__ __align__(128) float g_nd[NN];

__device__ int g_deg_d[NN], g_deg_s[NN];
__device__ int g_off_d[NN + 1], g_off_s[NN + 1];
__device__ int g_cur_d[NN], g_cur_s[NN];
__device__ int g_csr_src[EE];                 // by-dst: src list
__device__ int g_csr_dst[EE];                 // by-src: dst list
__device__ int g_bsum_d[256], g_bsum_s[256];

// ---------------------------------------------------------------------------
// Init: zero degree/cursor ints; seed BOTH z buffers:
//   masked rows  = labels (never overwritten later -> read-side select vanishes)
//   unmasked     = 0
// ---------------------------------------------------------------------------
__global__ void k_init(const int* __restrict__ mask, const float* __restrict__ labels) {
    int i = blockIdx.x * blockDim.x + threadIdx.x;
    if (i < NN) { g_deg_d[i] = 0; g_deg_s[i] = 0; g_cur_d[i] = 0; g_cur_s[i] = 0; }
    if (i < NN * CC) {
        int r = i / CC;
        float v = (__ldg(mask + r) != 0) ? labels[i] : 0.0f;
        g_z[0][i] = v;
        g_z[1][i] = v;
    }
}

__global__ void k_hist(const int* __restrict__ src, const int* __restrict__ dst) {
    int e = blockIdx.x * blockDim.x + threadIdx.x;
    if (e >= EE) return;
    atomicAdd(&g_deg_s[src[e]], 1);
    atomicAdd(&g_deg_d[dst[e]], 1);
}

__global__ void k_norm() {
    int i = blockIdx.x * blockDim.x + threadIdx.x;
    if (i >= NN) return;
    g_ns[i] = rsqrtf((float)max(g_deg_s[i], 1));
    g_nd[i] = rsqrtf((float)max(g_deg_d[i], 1));
}

// ---------------------------------------------------------------------------
// 3-kernel exclusive scan (n <= 256*256)
// ---------------------------------------------------------------------------
__global__ void k_scan1(const int* __restrict__ deg, int* __restrict__ bsum, int n) {
    __shared__ int s[256];
    int t = threadIdx.x, i = blockIdx.x * 256 + t;
    s[t] = (i < n) ? deg[i] : 0;
    __syncthreads();
    for (int o = 128; o > 0; o >>= 1) {
        if (t < o) s[t] += s[t + o];
        __syncthreads();
    }
    if (t == 0) bsum[blockIdx.x] = s[0];
}

__global__ void k_scan2(int* __restrict__ bsum, int nb) {
    __shared__ int s[256];
    int t = threadIdx.x;
    s[t] = (t < nb) ? bsum[t] : 0;
    __syncthreads();
    for (int o = 1; o < 256; o <<= 1) {
        int v = (t >= o) ? s[t - o] : 0;
        __syncthreads();
        s[t] += v;
        __syncthreads();
    }
    if (t < nb) bsum[t] = (t == 0) ? 0 : s[t - 1];
}

__global__ void k_scan3(const int* __restrict__ deg, const int* __restrict__ boff,
                        int* __restrict__ off, int n) {
    __shared__ int s[256];
    int t = threadIdx.x, i = blockIdx.x * 256 + t;
    int v = (i < n) ? deg[i] : 0;
    s[t] = v;
    __syncthreads();
    for (int o = 1; o < 256; o <<= 1) {
        int u = (t >= o) ? s[t - o] : 0;
        __syncthreads();
        s[t] += u;
        __syncthreads();
    }
    if (i < n) off[i] = boff[blockIdx.x] + s[t] - v;
    if (i == n - 1) off[n] = boff[blockIdx.x] + s[t];
}

__global__ void k_fill(const int* __restrict__ src, const int* __restrict__ dst) {
    int e = blockIdx.x * blockDim.x + threadIdx.x;
    if (e >= EE) return;
    int s = src[e], d = dst[e];
    int pd = g_off_d[d] + atomicAdd(&g_cur_d[d], 1);
    g_csr_src[pd] = s;
    int ps = g_off_s[s] + atomicAdd(&g_cur_s[s], 1);
    g_csr_dst[ps] = d;
}

// ---------------------------------------------------------------------------
// GEMM1: g_h1 = (features[NN,FIN] @ W1[FIN,HH]) * ns[row]
// 128x128x16 tiles, 256 threads, 8x8 microtile. Software-pipelined:
//   - B panel staged via cp.async (k-major already, no transpose)
//   - A panel prefetched into regs before compute, STS-transposed after
//   - double-buffered smem, single __syncthreads per k-tile
// ---------------------------------------------------------------------------
__global__ void __launch_bounds__(256, 2)
k_gemm1(const float* __restrict__ A, const float* __restrict__ B) {
    __shared__ __align__(16) float As[2][16][132];  // [buf][k][row]
    __shared__ __align__(16) float Bs[2][16][128];  // [buf][k][col]

    const int tid = threadIdx.x;
    const int bm0 = blockIdx.x * 128;
    const int tx = tid & 15, ty = tid >> 4;

    // Staging coordinates (2 float4 per thread for each of A and B)
    const int la0 = tid * 2, la1 = tid * 2 + 1;
    const int ar0 = la0 >> 2, ak0 = (la0 & 3) * 4;
    const int ar1 = la1 >> 2, ak1 = (la1 & 3) * 4;
    const bool av0 = (bm0 + ar0) < NN, av1 = (bm0 + ar1) < NN;
    const float* Ap0 = A + (size_t)(av0 ? bm0 + ar0 : 0) * FIN + ak0;
    const float* Ap1 = A + (size_t)(av1 ? bm0 + ar1 : 0) * FIN + ak1;
    const int bk0 = la0 >> 5, bc0 = (la0 & 31) * 4;
    const int bk1 = la1 >> 5, bc1 = (la1 & 31) * 4;
    const float* Bp0 = B + (size_t)bk0 * HH + bc0;
    const float* Bp1 = B + (size_t)bk1 * HH + bc1;

    float acc[8][8] = {};
    float4 pa0, pa1;
    const float4 zero4 = make_float4(0.f, 0.f, 0.f, 0.f);

    // --- prologue: stage tile 0 ---
    pa0 = av0 ? *(const float4*)Ap0 : zero4;
    pa1 = av1 ? *(const float4*)Ap1 : zero4;
    {
        unsigned s0 = (unsigned)__cvta_generic_to_shared(&Bs[0][bk0][bc0]);
        unsigned s1 = (unsigned)__cvta_generic_to_shared(&Bs[0][bk1][bc1]);
        asm volatile("cp.async.ca.shared.global [%0], [%1], 16;\n"
                     "cp.async.ca.shared.global [%2], [%3], 16;\n"
                     "cp.async.commit_group;\n"
                     :: "r"(s0), "l"(Bp0), "r"(s1), "l"(Bp1) : "memory");
    }
    As[0][ak0 + 0][ar0] = pa0.x; As[0][ak0 + 1][ar0] = pa0.y;
    As[0][ak0 + 2][ar0] = pa0.z; As[0][ak0 + 3][ar0] = pa0.w;
    As[0][ak1 + 0][ar1] = pa1.x; As[0][ak1 + 1][ar1] = pa1.y;
    As[0][ak1 + 2][ar1] = pa1.z; As[0][ak1 + 3][ar1] = pa1.w;
    asm volatile("cp.async.wait_group 0;" ::: "memory");
    __syncthreads();

    // --- main loop over 16 k-tiles ---
#pragma unroll 1
    for (int t = 0; t < FIN / 16; t++) {
        const int buf = t & 1, nbuf = buf ^ 1;
        const bool more = (t + 1) < FIN / 16;
        const int knext = (t + 1) * 16;

        if (more) {
            // issue global loads for next tile BEFORE compute
            pa0 = av0 ? *(const float4*)(Ap0 + knext) : zero4;
            pa1 = av1 ? *(const float4*)(Ap1 + knext) : zero4;
            unsigned s0 = (unsigned)__cvta_generic_to_shared(&Bs[nbuf][bk0][bc0]);
            unsigned s1 = (unsigned)__cvta_generic_to_shared(&Bs[nbuf][bk1][bc1]);
            const float* gb0 = Bp0 + (size_t)knext * HH;
            const float* gb1 = Bp1 + (size_t)knext * HH;
            asm volatile("cp.async.ca.shared.global [%0], [%1], 16;\n"
                         "cp.async.ca.shared.global [%2], [%3], 16;\n"
                         "cp.async.commit_group;\n"
                         :: "r"(s0), "l"(gb0), "r"(s1), "l"(gb1) : "memory");
        }

#pragma unroll
        for (int k = 0; k < 16; k++) {
            float4 a0 = *(const float4*)&As[buf][k][ty * 8];
            float4 a1 = *(const float4*)&As[buf][k][ty * 8 + 4];
            float4 b0 = *(const float4*)&Bs[buf][k][tx * 8];
            float4 b1 = *(const float4*)&Bs[buf][k][tx * 8 + 4];
            float ar[8] = {a0.x, a0.y, a0.z, a0.w, a1.x, a1.y, a1.z, a1.w};
            float br[8] = {b0.x, b0.y, b0.z, b0.w, b1.x, b1.y, b1.z, b1.w};
#pragma unroll
            for (int i = 0; i < 8; i++)
#pragma unroll
                for (int j = 0; j < 8; j++)
                    acc[i][j] += ar[i] * br[j];
        }

        if (more) {
            As[nbuf][ak0 + 0][ar0] = pa0.x; As[nbuf][ak0 + 1][ar0] = pa0.y;
            As[nbuf][ak0 + 2][ar0] = pa0.z; As[nbuf][ak0 + 3][ar0] = pa0.w;
            As[nbuf][ak1 + 0][ar1] = pa1.x; As[nbuf][ak1 + 1][ar1] = pa1.y;
            As[nbuf][ak1 + 2][ar1] = pa1.z; As[nbuf][ak1 + 3][ar1] = pa1.w;
            asm volatile("cp.async.wait_group 0;" ::: "memory");
        }
        __syncthreads();
    }

#pragma unroll
    for (int i = 0; i < 8; i++) {
        int r = bm0 + ty * 8 + i;
        if (r < NN) {
            float ns = g_ns[r];
            float4 o0 = make_float4(acc[i][0] * ns, acc[i][1] * ns,
                                    acc[i][2] * ns, acc[i][3] * ns);
            float4 o1 = make_float4(acc[i][4] * ns, acc[i][5] * ns,
                                    acc[i][6] * ns, acc[i][7] * ns);
            *(float4*)(g_h1 + (size_t)r * HH + tx * 8) = o0;
            *(float4*)(g_h1 + (size_t)r * HH + tx * 8 + 4) = o1;
        }
    }
}

// ---------------------------------------------------------------------------
// Aggregate L1 (by-dst CSR): agg1[n] = (sum h1[s]) * nd[n]
// Warp per node, 32 lanes x float4 = full 128-wide row per neighbor.
// ---------------------------------------------------------------------------
__global__ void k_agg1() {
    int w = (blockIdx.x * blockDim.x + threadIdx.x) >> 5;
    if (w >= NN) return;
    int lane = threadIdx.x & 31;
    int beg = g_off_d[w], end = g_off_d[w + 1];

    float4 acc = make_float4(0.f, 0.f, 0.f, 0.f);
    for (int base = beg; base < end; base += 32) {
        int idx = (base + lane < end) ? g_csr_src[base + lane] : 0;
        int m = min(32, end - base);
        for (int j = 0; j < m; j++) {
            int s = __shfl_sync(0xffffffffu, idx, j);
            float4 v = *(const float4*)(g_h1 + (size_t)s * HH + lane * 4);
            acc.x += v.x; acc.y += v.y; acc.z += v.z; acc.w += v.w;
        }
    }
    float nd = g_nd[w];
    acc.x *= nd; acc.y *= nd; acc.z *= nd; acc.w *= nd;
    *(float4*)(g_agg1 + (size_t)w * HH + lane * 4) = acc;
}

// ---------------------------------------------------------------------------
// GEMM2 fused: g_h2 = (relu(agg1 + b1) @ W2[HH,CC]) * ns
// 32 rows/block, 320 threads: thread = (row, 4-col group), float4 W reads.
// ---------------------------------------------------------------------------
__global__ void k_gemm2(const float* __restrict__ W2, const float* __restrict__ b1) {
    __shared__ __align__(16) float sW[HH * CC];   // 20 KB
    __shared__ __align__(16) float sX[32][HH];    // 16 KB

    const int tid = threadIdx.x;  // 320
    for (int i = tid; i < (HH * CC) / 4; i += 320)
        ((float4*)sW)[i] = ((const float4*)W2)[i];

    const int row0 = blockIdx.x * 32;
    for (int i = tid; i < 32 * HH / 4; i += 320) {
        int r = i >> 5, cq = i & 31;
        int gr = row0 + r;
        float4 v = make_float4(0.f, 0.f, 0.f, 0.f);
        if (gr < NN) {
            v = *(const float4*)(g_agg1 + (size_t)gr * HH + cq * 4);
            float4 bb = *(const float4*)(b1 + cq * 4);
            v.x = fmaxf(v.x + bb.x, 0.f);
            v.y = fmaxf(v.y + bb.y, 0.f);
            v.z = fmaxf(v.z + bb.z, 0.f);
            v.w = fmaxf(v.w + bb.w, 0.f);
        }
        *(float4*)&sX[r][cq * 4] = v;
    }
    __syncthreads();

    const int cj4 = tid % 10, ri = tid / 10;  // ri 0..31
    float4 acc = make_float4(0.f, 0.f, 0.f, 0.f);
#pragma unroll 8
    for (int k = 0; k < HH; k++) {
        float x = sX[ri][k];
        float4 wv = *(const float4*)&sW[k * CC + cj4 * 4];
        acc.x += x * wv.x; acc.y += x * wv.y;
        acc.z += x * wv.z; acc.w += x * wv.w;
    }
    int gr = row0 + ri;
    if (gr < NN) {
        float ns = g_ns[gr];
        acc.x *= ns; acc.y *= ns; acc.z *= ns; acc.w *= ns;
        *(float4*)(g_h2 + (size_t)gr * CC + cj4 * 4) = acc;
    }
}

// ---------------------------------------------------------------------------
// Aggregate L2 + epilogue: out_x[n] = (sum h2[s]) * nd[n] + b2
// Warp per node, 3 neighbors/step: lane = jsub*10 + c, float4 per lane.
// ---------------------------------------------------------------------------
__global__ void k_agg2(float* __restrict__ out, const float* __restrict__ b2) {
    int w = (blockIdx.x * blockDim.x + threadIdx.x) >> 5;
    if (w >= NN) return;
    int lane = threadIdx.x & 31;
    int jsub = lane / 10;              // 0..2 active, 3 = idle lanes 30,31
    int c = lane - jsub * 10;
    int beg = g_off_d[w], end = g_off_d[w + 1];

    float4 acc = make_float4(0.f, 0.f, 0.f, 0.f);
    for (int base = beg; base < end; base += 32) {
        int m = min(32, end - base);
        int idx = (base + lane < end) ? g_csr_src[base + lane] : 0;
        for (int t = 0; t * 3 < m; t++) {
            int j = t * 3 + jsub;
            int s = __shfl_sync(0xffffffffu, idx, j & 31);
            if (jsub < 3 && j < m) {
                float4 v = *(const float4*)(g_h2 + (size_t)s * CC + c * 4);
                acc.x += v.x; acc.y += v.y; acc.z += v.z; acc.w += v.w;
            }
        }
    }
    float4 s1, s2;
    s1.x = __shfl_down_sync(0xffffffffu, acc.x, 10);
    s1.y = __shfl_down_sync(0xffffffffu, acc.y, 10);
    s1.z = __shfl_down_sync(0xffffffffu, acc.z, 10);
    s1.w = __shfl_down_sync(0xffffffffu, acc.w, 10);
    s2.x = __shfl_down_sync(0xffffffffu, acc.x, 20);
    s2.y = __shfl_down_sync(0xffffffffu, acc.y, 20);
    s2.z = __shfl_down_sync(0xffffffffu, acc.z, 20);
    s2.w = __shfl_down_sync(0xffffffffu, acc.w, 20);
    if (lane < 10) {
        float nd = g_nd[w];
        float4 bb = *(const float4*)(b2 + lane * 4);
        float4 o;
        o.x = (acc.x + s1.x + s2.x) * nd + bb.x;
        o.y = (acc.y + s1.y + s2.y) * nd + bb.y;
        o.z = (acc.z + s1.z + s2.z) * nd + bb.z;
        o.w = (acc.w + s1.w + s2.w) * nd + bb.w;
        *(float4*)(out + (size_t)w * CC + lane * 4) = o;
    }
}

// ---------------------------------------------------------------------------
// LPA iteration (by-src CSR), unmasked sources only, plain zin reads
// (masked rows of z hold labels). 3 neighbors/step layout as in k_agg2.
// ---------------------------------------------------------------------------
__global__ void k_lpa(const int* __restrict__ mask, const float* __restrict__ zin,
                      float* __restrict__ zout) {
    int w = (blockIdx.x * blockDim.x + threadIdx.x) >> 5;
    if (w >= NN) return;
    if (__ldg(mask + w) != 0) return;   // masked rows never consumed
    int lane = threadIdx.x & 31;
    int jsub = lane / 10;
    int c = lane - jsub * 10;
    int beg = g_off_s[w], end = g_off_s[w + 1];

    float4 acc = make_float4(0.f, 0.f, 0.f, 0.f);
    for (int base = beg; base < end; base += 32) {
        int m = min(32, end - base);
        int idx = (base + lane < end) ? g_csr_dst[base + lane] : 0;
        for (int t = 0; t * 3 < m; t++) {
            int j = t * 3 + jsub;
            int d = __shfl_sync(0xffffffffu, idx, j & 31);
            if (jsub < 3 && j < m) {
                float4 v = *(const float4*)(zin + (size_t)d * CC + c * 4);
                acc.x += v.x; acc.y += v.y; acc.z += v.z; acc.w += v.w;
            }
        }
    }
    float4 s1, s2;
    s1.x = __shfl_down_sync(0xffffffffu, acc.x, 10);
    s1.y = __shfl_down_sync(0xffffffffu, acc.y, 10);
    s1.z = __shfl_down_sync(0xffffffffu, acc.z, 10);
    s1.w = __shfl_down_sync(0xffffffffu, acc.w, 10);
    s2.x = __shfl_down_sync(0xffffffffu, acc.x, 20);
    s2.y = __shfl_down_sync(0xffffffffu, acc.y, 20);
    s2.z = __shfl_down_sync(0xffffffffu, acc.z, 20);
    s2.w = __shfl_down_sync(0xffffffffu, acc.w, 20);
    if (lane < 10) {
        float4 o;
        o.x = acc.x + s1.x + s2.x;
        o.y = acc.y + s1.y + s2.y;
        o.z = acc.z + s1.z + s2.z;
        o.w = acc.w + s1.w + s2.w;
        *(float4*)(zout + (size_t)w * CC + lane * 4) = o;
    }
}

// Fill masked output rows with labels (unmasked written by final k_lpa)
__global__ void k_epi_mask(float* __restrict__ out, const float* __restrict__ labels,
                           const int* __restrict__ mask) {
    int i = blockIdx.x * blockDim.x + threadIdx.x;
    if (i >= NN * CC) return;
    int r = i / CC;
    if (__ldg(mask + r) != 0) out[NN * CC + i] = labels[i];
}

// ---------------------------------------------------------------------------
// Launch
// ---------------------------------------------------------------------------
extern "C" void kernel_launch(void* const* d_in, const int* in_sizes, int n_in,
                              void* d_out, int out_size) {
    const float* feat   = (const float*)d_in[0];
    const float* labels = (const float*)d_in[1];
    const int*   mask   = (const int*)d_in[2];
    const int*   src    = (const int*)d_in[3];
    const int*   dst    = (const int*)d_in[4];
    const float* W1     = (const float*)d_in[5];
    const float* b1     = (const float*)d_in[6];
    const float* W2     = (const float*)d_in[7];
    const float* b2     = (const float*)d_in[8];
    float*       out    = (float*)d_out;

    const int T = 256;
    auto blks = [](long long n, int t) { return (int)((n + t - 1) / t); };

    void *p_deg_d, *p_deg_s, *p_off_d, *p_off_s, *p_bs_d, *p_bs_s, *p_z;
    cudaGetSymbolAddress(&p_deg_d, g_deg_d);
    cudaGetSymbolAddress(&p_deg_s, g_deg_s);
    cudaGetSymbolAddress(&p_off_d, g_off_d);
    cudaGetSymbolAddress(&p_off_s, g_off_s);
    cudaGetSymbolAddress(&p_bs_d, g_bsum_d);
    cudaGetSymbolAddress(&p_bs_s, g_bsum_s);
    cudaGetSymbolAddress(&p_z, g_z);
    float* z0 = (float*)p_z;
    float* z1 = z0 + (size_t)NN * CC;

    // 1-3: init + degrees + norms
    k_init<<<blks((long long)NN * CC, T), T>>>(mask, labels);
    k_hist<<<blks(EE, T), T>>>(src, dst);
    k_norm<<<blks(NN, T), T>>>();

    // 4: GEMM1 (kept 4th so ncu's capture window hits it)
    k_gemm1<<<blks(NN, 128), 256>>>(feat, W1);

    // CSR build
    k_scan1<<<NB, 256>>>((const int*)p_deg_d, (int*)p_bs_d, NN);
    k_scan2<<<1, 256>>>((int*)p_bs_d, NB);
    k_scan3<<<NB, 256>>>((const int*)p_deg_d, (const int*)p_bs_d, (int*)p_off_d, NN);
    k_scan1<<<NB, 256>>>((const int*)p_deg_s, (int*)p_bs_s, NN);
    k_scan2<<<1, 256>>>((int*)p_bs_s, NB);
    k_scan3<<<NB, 256>>>((const int*)p_deg_s, (const int*)p_bs_s, (int*)p_off_s, NN);
    k_fill<<<blks(EE, T), T>>>(src, dst);

    // GCN
    k_agg1<<<blks((long long)NN * 32, T), T>>>();
    k_gemm2<<<blks(NN, 32), 320>>>(W2, b1);
    k_agg2<<<blks((long long)NN * 32, T), T>>>(out, b2);

    // LPA: ping-pong, final iteration writes straight into out
    for (int it = 0; it < LPA_ITERS; it++) {
        float* zin  = (it & 1) ? z1 : z0;
        float* zout = (it == LPA_ITERS - 1) ? (out + (size_t)NN * CC)
                                            : ((it & 1) ? z0 : z1);
        k_lpa<<<blks((long long)NN * 32, T), T>>>(mask, zin, zout);
    }
    k_epi_mask<<<blks((long long)NN * CC, T), T>>>(out, labels, mask);
}

// round 16
// speedup vs baseline: 1.0253x; 1.0005x over previous
#include <cuda_runtime.h>

// Problem constants (fixed by the reference)
#define NN  50000
#define EE  800000
#define FIN 256
#define HH  128
#define CC  40
#define LPA_ITERS 10
#define NB  ((NN + 255) / 256)   // 196 scan blocks

// ---------------------------------------------------------------------------
// Device scratch (no allocations allowed)
// ---------------------------------------------------------------------------
__device__ __align__(128) float g_h1[(size_t)NN * HH];    // (features@W1)*ns
__device__ __align__(128) float g_agg1[(size_t)NN * HH];  // aggregated L1 (*nd fused)
__device__ __align__(128) float g_h2[(size_t)NN * CC];    // (x1@W2)*ns
__device__ __align__(128) float g_z[2][(size_t)NN * CC];  // LPA ping-pong
__device__ __align__(128) float g_ns[NN];
__device__ __align__(128) float g_nd[NN];

__device__ int g_deg_d[NN], g_deg_s[NN];
__device__ int g_off_d[NN + 1], g_off_s[NN + 1];
__device__ int g_cur_d[NN], g_cur_s[NN];
__device__ int g_csr_src[EE];                 // by-dst: src list
__device__ int g_csr_dst[EE];                 // by-src: dst list
__device__ int g_bsum_d[256], g_bsum_s[256];

// ---------------------------------------------------------------------------
// Init: zero degree/cursor ints; seed BOTH z buffers:
//   masked rows  = labels (never overwritten later -> read-side select vanishes)
//   unmasked     = 0
// ---------------------------------------------------------------------------
__global__ void k_init(const int* __restrict__ mask, const float* __restrict__ labels) {
    int i = blockIdx.x * blockDim.x + threadIdx.x;
    if (i < NN) { g_deg_d[i] = 0; g_deg_s[i] = 0; g_cur_d[i] = 0; g_cur_s[i] = 0; }
    if (i < NN * CC) {
        int r = i / CC;
        float v = (__ldg(mask + r) != 0) ? labels[i] : 0.0f;
        g_z[0][i] = v;
        g_z[1][i] = v;
    }
}

__global__ void k_hist(const int* __restrict__ src, const int* __restrict__ dst) {
    int e = blockIdx.x * blockDim.x + threadIdx.x;
    if (e >= EE) return;
    atomicAdd(&g_deg_s[src[e]], 1);
    atomicAdd(&g_deg_d[dst[e]], 1);
}

__global__ void k_norm() {
    int i = blockIdx.x * blockDim.x + threadIdx.x;
    if (i >= NN) return;
    g_ns[i] = rsqrtf((float)max(g_deg_s[i], 1));
    g_nd[i] = rsqrtf((float)max(g_deg_d[i], 1));
}

// ---------------------------------------------------------------------------
// 3-kernel exclusive scan (n <= 256*256)
// ---------------------------------------------------------------------------
__global__ void k_scan1(const int* __restrict__ deg, int* __restrict__ bsum, int n) {
    __shared__ int s[256];
    int t = threadIdx.x, i = blockIdx.x * 256 + t;
    s[t] = (i < n) ? deg[i] : 0;
    __syncthreads();
    for (int o = 128; o > 0; o >>= 1) {
        if (t < o) s[t] += s[t + o];
        __syncthreads();
    }
    if (t == 0) bsum[blockIdx.x] = s[0];
}

__global__ void k_scan2(int* __restrict__ bsum, int nb) {
    __shared__ int s[256];
    int t = threadIdx.x;
    s[t] = (t < nb) ? bsum[t] : 0;
    __syncthreads();
    for (int o = 1; o < 256; o <<= 1) {
        int v = (t >= o) ? s[t - o] : 0;
        __syncthreads();
        s[t] += v;
        __syncthreads();
    }
    if (t < nb) bsum[t] = (t == 0) ? 0 : s[t - 1];
}

__global__ void k_scan3(const int* __restrict__ deg, const int* __restrict__ boff,
                        int* __restrict__ off, int n) {
    __shared__ int s[256];
    int t = threadIdx.x, i = blockIdx.x * 256 + t;
    int v = (i < n) ? deg[i] : 0;
    s[t] = v;
    __syncthreads();
    for (int o = 1; o < 256; o <<= 1) {
        int u = (t >= o) ? s[t - o] : 0;
        __syncthreads();
        s[t] += u;
        __syncthreads();
    }
    if (i < n) off[i] = boff[blockIdx.x] + s[t] - v;
    if (i == n - 1) off[n] = boff[blockIdx.x] + s[t];
}

__global__ void k_fill(const int* __restrict__ src, const int* __restrict__ dst) {
    int e = blockIdx.x * blockDim.x + threadIdx.x;
    if (e >= EE) return;
    int s = src[e], d = dst[e];
    int pd = g_off_d[d] + atomicAdd(&g_cur_d[d], 1);
    g_csr_src[pd] = s;
    int ps = g_off_s[s] + atomicAdd(&g_cur_s[s], 1);
    g_csr_dst[ps] = d;
}

// ---------------------------------------------------------------------------
// GEMM1: g_h1 = (features[NN,FIN] @ W1[FIN,HH]) * ns[row]
// 128x128x16 tiles, 256 threads, 8x8 microtile. Software-pipelined:
//   - B panel staged via cp.async (k-major already, no transpose)
//   - A panel prefetched into regs before compute, STS-transposed after
//   - double-buffered smem, single __syncthreads per k-tile
// ---------------------------------------------------------------------------
__global__ void __launch_bounds__(256, 2)
k_gemm1(const float* __restrict__ A, const float* __restrict__ B) {
    __shared__ __align__(16) float As[2][16][132];  // [buf][k][row]
    __shared__ __align__(16) float Bs[2][16][128];  // [buf][k][col]

    const int tid = threadIdx.x;
    const int bm0 = blockIdx.x * 128;
    const int tx = tid & 15, ty = tid >> 4;

    // Staging coordinates (2 float4 per thread for each of A and B)
    const int la0 = tid * 2, la1 = tid * 2 + 1;
    const int ar0 = la0 >> 2, ak0 = (la0 & 3) * 4;
    const int ar1 = la1 >> 2, ak1 = (la1 & 3) * 4;
    const bool av0 = (bm0 + ar0) < NN, av1 = (bm0 + ar1) < NN;
    const float* Ap0 = A + (size_t)(av0 ? bm0 + ar0 : 0) * FIN + ak0;
    const float* Ap1 = A + (size_t)(av1 ? bm0 + ar1 : 0) * FIN + ak1;
    const int bk0 = la0 >> 5, bc0 = (la0 & 31) * 4;
    const int bk1 = la1 >> 5, bc1 = (la1 & 31) * 4;
    const float* Bp0 = B + (size_t)bk0 * HH + bc0;
    const float* Bp1 = B + (size_t)bk1 * HH + bc1;

    float acc[8][8] = {};
    float4 pa0, pa1;
    const float4 zero4 = make_float4(0.f, 0.f, 0.f, 0.f);

    // --- prologue: stage tile 0 ---
    pa0 = av0 ? *(const float4*)Ap0 : zero4;
    pa1 = av1 ? *(const float4*)Ap1 : zero4;
    {
        unsigned s0 = (unsigned)__cvta_generic_to_shared(&Bs[0][bk0][bc0]);
        unsigned s1 = (unsigned)__cvta_generic_to_shared(&Bs[0][bk1][bc1]);
        asm volatile("cp.async.ca.shared.global [%0], [%1], 16;\n"
                     "cp.async.ca.shared.global [%2], [%3], 16;\n"
                     "cp.async.commit_group;\n"
                     :: "r"(s0), "l"(Bp0), "r"(s1), "l"(Bp1) : "memory");
    }
    As[0][ak0 + 0][ar0] = pa0.x; As[0][ak0 + 1][ar0] = pa0.y;
    As[0][ak0 + 2][ar0] = pa0.z; As[0][ak0 + 3][ar0] = pa0.w;
    As[0][ak1 + 0][ar1] = pa1.x; As[0][ak1 + 1][ar1] = pa1.y;
    As[0][ak1 + 2][ar1] = pa1.z; As[0][ak1 + 3][ar1] = pa1.w;
    asm volatile("cp.async.wait_group 0;" ::: "memory");
    __syncthreads();

    // --- main loop over 16 k-tiles ---
#pragma unroll 1
    for (int t = 0; t < FIN / 16; t++) {
        const int buf = t & 1, nbuf = buf ^ 1;
        const bool more = (t + 1) < FIN / 16;
        const int knext = (t + 1) * 16;

        if (more) {
            // issue global loads for next tile BEFORE compute
            pa0 = av0 ? *(const float4*)(Ap0 + knext) : zero4;
            pa1 = av1 ? *(const float4*)(Ap1 + knext) : zero4;
            unsigned s0 = (unsigned)__cvta_generic_to_shared(&Bs[nbuf][bk0][bc0]);
            unsigned s1 = (unsigned)__cvta_generic_to_shared(&Bs[nbuf][bk1][bc1]);
            const float* gb0 = Bp0 + (size_t)knext * HH;
            const float* gb1 = Bp1 + (size_t)knext * HH;
            asm volatile("cp.async.ca.shared.global [%0], [%1], 16;\n"
                         "cp.async.ca.shared.global [%2], [%3], 16;\n"
                         "cp.async.commit_group;\n"
                         :: "r"(s0), "l"(gb0), "r"(s1), "l"(gb1) : "memory");
        }

#pragma unroll
        for (int k = 0; k < 16; k++) {
            float4 a0 = *(const float4*)&As[buf][k][ty * 8];
            float4 a1 = *(const float4*)&As[buf][k][ty * 8 + 4];
            float4 b0 = *(const float4*)&Bs[buf][k][tx * 8];
            float4 b1 = *(const float4*)&Bs[buf][k][tx * 8 + 4];
            float ar[8] = {a0.x, a0.y, a0.z, a0.w, a1.x, a1.y, a1.z, a1.w};
            float br[8] = {b0.x, b0.y, b0.z, b0.w, b1.x, b1.y, b1.z, b1.w};
#pragma unroll
            for (int i = 0; i < 8; i++)
#pragma unroll
                for (int j = 0; j < 8; j++)
                    acc[i][j] += ar[i] * br[j];
        }

        if (more) {
            As[nbuf][ak0 + 0][ar0] = pa0.x; As[nbuf][ak0 + 1][ar0] = pa0.y;
            As[nbuf][ak0 + 2][ar0] = pa0.z; As[nbuf][ak0 + 3][ar0] = pa0.w;
            As[nbuf][ak1 + 0][ar1] = pa1.x; As[nbuf][ak1 + 1][ar1] = pa1.y;
            As[nbuf][ak1 + 2][ar1] = pa1.z; As[nbuf][ak1 + 3][ar1] = pa1.w;
            asm volatile("cp.async.wait_group 0;" ::: "memory");
        }
        __syncthreads();
    }

#pragma unroll
    for (int i = 0; i < 8; i++) {
        int r = bm0 + ty * 8 + i;
        if (r < NN) {
            float ns = g_ns[r];
            float4 o0 = make_float4(acc[i][0] * ns, acc[i][1] * ns,
                                    acc[i][2] * ns, acc[i][3] * ns);
            float4 o1 = make_float4(acc[i][4] * ns, acc[i][5] * ns,
                                    acc[i][6] * ns, acc[i][7] * ns);
            *(float4*)(g_h1 + (size_t)r * HH + tx * 8) = o0;
            *(float4*)(g_h1 + (size_t)r * HH + tx * 8 + 4) = o1;
        }
    }
}

// ---------------------------------------------------------------------------
// Aggregate L1 (by-dst CSR): agg1[n] = (sum h1[s]) * nd[n]
// Warp per node, 32 lanes x float4 = full 128-wide row per neighbor.
// ---------------------------------------------------------------------------
__global__ void k_agg1() {
    int w = (blockIdx.x * blockDim.x + threadIdx.x) >> 5;
    if (w >= NN) return;
    int lane = threadIdx.x & 31;
    int beg = g_off_d[w], end = g_off_d[w + 1];

    float4 acc = make_float4(0.f, 0.f, 0.f, 0.f);
    for (int base = beg; base < end; base += 32) {
        int idx = (base + lane < end) ? g_csr_src[base + lane] : 0;
        int m = min(32, end - base);
        for (int j = 0; j < m; j++) {
            int s = __shfl_sync(0xffffffffu, idx, j);
            float4 v = *(const float4*)(g_h1 + (size_t)s * HH + lane * 4);
            acc.x += v.x; acc.y += v.y; acc.z += v.z; acc.w += v.w;
        }
    }
    float nd = g_nd[w];
    acc.x *= nd; acc.y *= nd; acc.z *= nd; acc.w *= nd;
    *(float4*)(g_agg1 + (size_t)w * HH + lane * 4) = acc;
}

// ---------------------------------------------------------------------------
// GEMM2 fused: g_h2 = (relu(agg1 + b1) @ W2[HH,CC]) * ns
// 32 rows/block, 320 threads: thread = (row, 4-col group), float4 W reads.
// ---------------------------------------------------------------------------
__global__ void k_gemm2(const float* __restrict__ W2, const float* __restrict__ b1) {
    __shared__ __align__(16) float sW[HH * CC];   // 20 KB
    __shared__ __align__(16) float sX[32][HH];    // 16 KB

    const int tid = threadIdx.x;  // 320
    for (int i = tid; i < (HH * CC) / 4; i += 320)
        ((float4*)sW)[i] = ((const float4*)W2)[i];

    const int row0 = blockIdx.x * 32;
    for (int i = tid; i < 32 * HH / 4; i += 320) {
        int r = i >> 5, cq = i & 31;
        int gr = row0 + r;
        float4 v = make_float4(0.f, 0.f, 0.f, 0.f);
        if (gr < NN) {
            v = *(const float4*)(g_agg1 + (size_t)gr * HH + cq * 4);
            float4 bb = *(const float4*)(b1 + cq * 4);
            v.x = fmaxf(v.x + bb.x, 0.f);
            v.y = fmaxf(v.y + bb.y, 0.f);
            v.z = fmaxf(v.z + bb.z, 0.f);
            v.w = fmaxf(v.w + bb.w, 0.f);
        }
        *(float4*)&sX[r][cq * 4] = v;
    }
    __syncthreads();

    const int cj4 = tid % 10, ri = tid / 10;  // ri 0..31
    float4 acc = make_float4(0.f, 0.f, 0.f, 0.f);
#pragma unroll 8
    for (int k = 0; k < HH; k++) {
        float x = sX[ri][k];
        float4 wv = *(const float4*)&sW[k * CC + cj4 * 4];
        acc.x += x * wv.x; acc.y += x * wv.y;
        acc.z += x * wv.z; acc.w += x * wv.w;
    }
    int gr = row0 + ri;
    if (gr < NN) {
        float ns = g_ns[gr];
        acc.x *= ns; acc.y *= ns; acc.z *= ns; acc.w *= ns;
        *(float4*)(g_h2 + (size_t)gr * CC + cj4 * 4) = acc;
    }
}

// ---------------------------------------------------------------------------
// Aggregate L2 + epilogue: out_x[n] = (sum h2[s]) * nd[n] + b2
// Warp per node, 3 neighbors/step: lane = jsub*10 + c, float4 per lane.
// ---------------------------------------------------------------------------
__global__ void k_agg2(float* __restrict__ out, const float* __restrict__ b2) {
    int w = (blockIdx.x * blockDim.x + threadIdx.x) >> 5;
    if (w >= NN) return;
    int lane = threadIdx.x & 31;
    int jsub = lane / 10;              // 0..2 active, 3 = idle lanes 30,31
    int c = lane - jsub * 10;
    int beg = g_off_d[w], end = g_off_d[w + 1];

    float4 acc = make_float4(0.f, 0.f, 0.f, 0.f);
    for (int base = beg; base < end; base += 32) {
        int m = min(32, end - base);
        int idx = (base + lane < end) ? g_csr_src[base + lane] : 0;
        for (int t = 0; t * 3 < m; t++) {
            int j = t * 3 + jsub;
            int s = __shfl_sync(0xffffffffu, idx, j & 31);
            if (jsub < 3 && j < m) {
                float4 v = *(const float4*)(g_h2 + (size_t)s * CC + c * 4);
                acc.x += v.x; acc.y += v.y; acc.z += v.z; acc.w += v.w;
            }
        }
    }
    float4 s1, s2;
    s1.x = __shfl_down_sync(0xffffffffu, acc.x, 10);
    s1.y = __shfl_down_sync(0xffffffffu, acc.y, 10);
    s1.z = __shfl_down_sync(0xffffffffu, acc.z, 10);
    s1.w = __shfl_down_sync(0xffffffffu, acc.w, 10);
    s2.x = __shfl_down_sync(0xffffffffu, acc.x, 20);
    s2.y = __shfl_down_sync(0xffffffffu, acc.y, 20);
    s2.z = __shfl_down_sync(0xffffffffu, acc.z, 20);
    s2.w = __shfl_down_sync(0xffffffffu, acc.w, 20);
    if (lane < 10) {
        float nd = g_nd[w];
        float4 bb = *(const float4*)(b2 + lane * 4);
        float4 o;
        o.x = (acc.x + s1.x + s2.x) * nd + bb.x;
        o.y = (acc.y + s1.y + s2.y) * nd + bb.y;
        o.z = (acc.z + s1.z + s2.z) * nd + bb.z;
        o.w = (acc.w + s1.w + s2.w) * nd + bb.w;
        *(float4*)(out + (size_t)w * CC + lane * 4) = o;
    }
}

// ---------------------------------------------------------------------------
// LPA iteration (by-src CSR), unmasked sources only, plain zin reads
// (masked rows of z hold labels). 3 neighbors/step layout as in k_agg2.
// ---------------------------------------------------------------------------
__global__ void k_lpa(const int* __restrict__ mask, const float* __restrict__ zin,
                      float* __restrict__ zout) {
    int w = (blockIdx.x * blockDim.x + threadIdx.x) >> 5;
    if (w >= NN) return;
    if (__ldg(mask + w) != 0) return;   // masked rows never consumed
    int lane = threadIdx.x & 31;
    int jsub = lane / 10;
    int c = lane - jsub * 10;
    int beg = g_off_s[w], end = g_off_s[w + 1];

    float4 acc = make_float4(0.f, 0.f, 0.f, 0.f);
    for (int base = beg; base < end; base += 32) {
        int m = min(32, end - base);
        int idx = (base + lane < end) ? g_csr_dst[base + lane] : 0;
        for (int t = 0; t * 3 < m; t++) {
            int j = t * 3 + jsub;
            int d = __shfl_sync(0xffffffffu, idx, j & 31);
            if (jsub < 3 && j < m) {
                float4 v = *(const float4*)(zin + (size_t)d * CC + c * 4);
                acc.x += v.x; acc.y += v.y; acc.z += v.z; acc.w += v.w;
            }
        }
    }
    float4 s1, s2;
    s1.x = __shfl_down_sync(0xffffffffu, acc.x, 10);
    s1.y = __shfl_down_sync(0xffffffffu, acc.y, 10);
    s1.z = __shfl_down_sync(0xffffffffu, acc.z, 10);
    s1.w = __shfl_down_sync(0xffffffffu, acc.w, 10);
    s2.x = __shfl_down_sync(0xffffffffu, acc.x, 20);
    s2.y = __shfl_down_sync(0xffffffffu, acc.y, 20);
    s2.z = __shfl_down_sync(0xffffffffu, acc.z, 20);
    s2.w = __shfl_down_sync(0xffffffffu, acc.w, 20);
    if (lane < 10) {
        float4 o;
        o.x = acc.x + s1.x + s2.x;
        o.y = acc.y + s1.y + s2.y;
        o.z = acc.z + s1.z + s2.z;
        o.w = acc.w + s1.w + s2.w;
        *(float4*)(zout + (size_t)w * CC + lane * 4) = o;
    }
}

// Fill masked output rows with labels (unmasked written by final k_lpa)
__global__ void k_epi_mask(float* __restrict__ out, const float* __restrict__ labels,
                           const int* __restrict__ mask) {
    int i = blockIdx.x * blockDim.x + threadIdx.x;
    if (i >= NN * CC) return;
    int r = i / CC;
    if (__ldg(mask + r) != 0) out[NN * CC + i] = labels[i];
}

// ---------------------------------------------------------------------------
// Launch
// ---------------------------------------------------------------------------
extern "C" void kernel_launch(void* const* d_in, const int* in_sizes, int n_in,
                              void* d_out, int out_size) {
    const float* feat   = (const float*)d_in[0];
    const float* labels = (const float*)d_in[1];
    const int*   mask   = (const int*)d_in[2];
    const int*   src    = (const int*)d_in[3];
    const int*   dst    = (const int*)d_in[4];
    const float* W1     = (const float*)d_in[5];
    const float* b1     = (const float*)d_in[6];
    const float* W2     = (const float*)d_in[7];
    const float* b2     = (const float*)d_in[8];
    float*       out    = (float*)d_out;

    const int T = 256;
    auto blks = [](long long n, int t) { return (int)((n + t - 1) / t); };

    void *p_deg_d, *p_deg_s, *p_off_d, *p_off_s, *p_bs_d, *p_bs_s, *p_z;
    cudaGetSymbolAddress(&p_deg_d, g_deg_d);
    cudaGetSymbolAddress(&p_deg_s, g_deg_s);
    cudaGetSymbolAddress(&p_off_d, g_off_d);
    cudaGetSymbolAddress(&p_off_s, g_off_s);
    cudaGetSymbolAddress(&p_bs_d, g_bsum_d);
    cudaGetSymbolAddress(&p_bs_s, g_bsum_s);
    cudaGetSymbolAddress(&p_z, g_z);
    float* z0 = (float*)p_z;
    float* z1 = z0 + (size_t)NN * CC;

    // 1-3: init + degrees + norms
    k_init<<<blks((long long)NN * CC, T), T>>>(mask, labels);
    k_hist<<<blks(EE, T), T>>>(src, dst);
    k_norm<<<blks(NN, T), T>>>();

    // 4: GEMM1 (kept 4th so ncu's capture window hits it)
    k_gemm1<<<blks(NN, 128), 256>>>(feat, W1);

    // CSR build
    k_scan1<<<NB, 256>>>((const int*)p_deg_d, (int*)p_bs_d, NN);
    k_scan2<<<1, 256>>>((int*)p_bs_d, NB);
    k_scan3<<<NB, 256>>>((const int*)p_deg_d, (const int*)p_bs_d, (int*)p_off_d, NN);
    k_scan1<<<NB, 256>>>((const int*)p_deg_s, (int*)p_bs_s, NN);
    k_scan2<<<1, 256>>>((int*)p_bs_s, NB);
    k_scan3<<<NB, 256>>>((const int*)p_deg_s, (const int*)p_bs_s, (int*)p_off_s, NN);
    k_fill<<<blks(EE, T), T>>>(src, dst);

    // GCN
    k_agg1<<<blks((long long)NN * 32, T), T>>>();
    k_gemm2<<<blks(NN, 32), 320>>>(W2, b1);
    k_agg2<<<blks((long long)NN * 32, T), T>>>(out, b2);

    // LPA: ping-pong, final iteration writes straight into out
    for (int it = 0; it < LPA_ITERS; it++) {
        float* zin  = (it & 1) ? z1 : z0;
        float* zout = (it == LPA_ITERS - 1) ? (out + (size_t)NN * CC)
                                            : ((it & 1) ? z0 : z1);
        k_lpa<<<blks((long long)NN * 32, T), T>>>(mask, zin, zout);
    }
    k_epi_mask<<<blks((long long)NN * CC, T), T>>>(out, labels, mask);
}